// round 8
// baseline (speedup 1.0000x reference)
#include <cuda_runtime.h>
#include <cuda_bf16.h>
#include <cstdint>

// BahdanauAttention with size-1 attention axis:
//   softmax over length-1 axis == 1.0 -> attention_weights = ones
//   context = features (bit-exact copy). Score GEMMs are dead code.
// Pure HBM streaming copy: 128 MiB read + 128 MiB write + 64 KiB fill.
//
// State of play: 36.4us kernel = 7.38 TB/s = 92% of HBM spec. Confirmed
// NOT latency-bound (occ 78%->21% at fixed bandwidth). This round tests
// the last knob: streaming hint on STORES ONLY (__stcs), so L2 evicts
// never-reread write lines early. Loads stay default (load-side .cs
// hurt in round 2).

static constexpr int Bsz = 16384;
static constexpr int Dsz = 2048;
static constexpr int CTX_VECS = (Bsz * Dsz) / 4;   // 8,388,608 float4 (2^23)
static constexpr int AW_VECS  = Bsz / 4;           // 4,096 float4

static constexpr int THREADS = 256;
static constexpr int BLOCKS  = 2048;
static constexpr int NTHREADS = THREADS * BLOCKS;           // 524,288 = 2^19
static constexpr int VECS_PER_THREAD = CTX_VECS / NTHREADS; // 16, exact

__global__ void __launch_bounds__(THREADS, 2)
bahdanau_copy_kernel(const float4* __restrict__ features, float4* __restrict__ out) {
    int tid = blockIdx.x * THREADS + threadIdx.x;

    // All 16 loads issued before any store (true MLP=16, regs ~86).
    float4 a[VECS_PER_THREAD];
    #pragma unroll
    for (int j = 0; j < VECS_PER_THREAD; j++)
        a[j] = features[tid + j * NTHREADS];
    #pragma unroll
    for (int j = 0; j < VECS_PER_THREAD; j++)
        __stcs(&out[tid + j * NTHREADS], a[j]);

    // Trailing ones for attention_weights: one extra store for 4096 threads.
    if (tid < AW_VECS) {
        __stcs(&out[CTX_VECS + tid], make_float4(1.f, 1.f, 1.f, 1.f));
    }
}

extern "C" void kernel_launch(void* const* d_in, const int* in_sizes, int n_in,
                              void* d_out, int out_size) {
    const float4* features = (const float4*)d_in[0];
    float4* out = (float4*)d_out;
    bahdanau_copy_kernel<<<BLOCKS, THREADS>>>(features, out);
}